// round 15
// baseline (speedup 1.0000x reference)
#include <cuda_runtime.h>
#include <cuda_bf16.h>
#include <math.h>

#define N 4096
#define G (3 * N)
#define CCHUNK 32          // rows per colmv block

// ---------------- device scratch ----------------
__device__ float g_t[N];        // logits buffer
__device__ float g_sk[N];       // GRU hidden state
__device__ float g_u[N];        // u = W2 @ sk
__device__ float g_xk[N];       // x_k
__device__ float g_gi[G];       // w_ih @ xk
__device__ float g_gh[G];       // w_hh @ sk
__device__ float g_stats[2];    // [max, 1/sum] of current logits
__device__ float g_l3[8 * 3];   // per-step label logits

// bf16 copies (gates + post-softmax M_p: all safe, downstream of exp / behind
// saturating nonlinearities; the logits-path M_p stays fp32 — R12 proved it must)
__device__ __nv_bfloat16 g_wih_bf[(size_t)G * N];   // 96 MB
__device__ __nv_bfloat16 g_whh_bf[(size_t)G * N];   // 96 MB
__device__ __nv_bfloat16 g_mp_bf[(size_t)N * N];    // 32 MB (xk pass only)

// ---------------- kernels ----------------

__global__ void init_kernel() {
    int i = blockIdx.x * blockDim.x + threadIdx.x;
    if (i < N) g_t[i] = 0.0f;
    if (i < 24) g_l3[i] = 0.0f;
}

// fp32 -> bf16 conversion, 8 elements/thread, streaming (don't pollute L2)
__global__ void convert_bf16_kernel(const float* __restrict__ src,
                                    __nv_bfloat16* __restrict__ dst,
                                    int n8) {
    int idx = blockIdx.x * blockDim.x + threadIdx.x;
    if (idx >= n8) return;
    const float4* s4 = (const float4*)src;
    float4 a = __ldcs(&s4[2 * idx]);
    float4 b = __ldcs(&s4[2 * idx + 1]);
    __nv_bfloat162 p0 = __floats2bfloat162_rn(a.x, a.y);
    __nv_bfloat162 p1 = __floats2bfloat162_rn(a.z, a.w);
    __nv_bfloat162 p2 = __floats2bfloat162_rn(b.x, b.y);
    __nv_bfloat162 p3 = __floats2bfloat162_rn(b.z, b.w);
    uint4 out;
    out.x = *(unsigned int*)&p0;
    out.y = *(unsigned int*)&p1;
    out.z = *(unsigned int*)&p2;
    out.w = *(unsigned int*)&p3;
    __stcs((uint4*)dst + idx, out);
}

// y[j] += sum_r x[r] * A[r, j]   (fp32; default caching -> A stays L2-resident)
// grid: (16, 128) = 2048 blocks, block: 256
__global__ void colmv_kernel(const float* __restrict__ A,
                             const float* __restrict__ x,
                             float* __restrict__ y,
                             int step, const int* __restrict__ Kp) {
    if (step >= *Kp) return;
    __shared__ float xs[CCHUNK];
    int j = blockIdx.x * blockDim.x + threadIdx.x;
    int r0 = blockIdx.y * CCHUNK;
    if (threadIdx.x < CCHUNK) xs[threadIdx.x] = x[r0 + threadIdx.x];
    __syncthreads();
    const float* Ap = A + (size_t)r0 * N + j;
    float acc = 0.0f;
#pragma unroll
    for (int r = 0; r < CCHUNK; r++)
        acc += xs[r] * Ap[(size_t)r * N];
    atomicAdd(&y[j], acc);
}

// fp32 colmv_exp (prologue M_h only): weights = exp(t-M)*invS from g_stats
__global__ void colmv_exp_kernel(const float* __restrict__ A,
                                 const float* __restrict__ t,
                                 float* __restrict__ y,
                                 int step, const int* __restrict__ Kp) {
    if (step >= *Kp) return;
    __shared__ float xs[CCHUNK];
    int j = blockIdx.x * blockDim.x + threadIdx.x;
    int r0 = blockIdx.y * CCHUNK;
    if (threadIdx.x < CCHUNK) {
        float M = g_stats[0], invS = g_stats[1];
        xs[threadIdx.x] = expf(t[r0 + threadIdx.x] - M) * invS;
    }
    __syncthreads();
    const float* Ap = A + (size_t)r0 * N + j;
    float acc = 0.0f;
#pragma unroll
    for (int r = 0; r < CCHUNK; r++)
        acc += xs[r] * Ap[(size_t)r * N];
    atomicAdd(&y[j], acc);
}

// bf16 colmv_exp (xk pass): y += softmax(t) @ A_bf. Default-cached loads:
// mp_bf is read every step and should stay L2-resident.
// grid: (N/512 = 8, 128) = 1024 blocks, block: 256 (2 columns/thread)
__global__ void colmv_exp_bf16_kernel(const __nv_bfloat16* __restrict__ A,
                                      const float* __restrict__ t,
                                      float* __restrict__ y,
                                      int step, const int* __restrict__ Kp) {
    if (step >= *Kp) return;
    __shared__ float xs[CCHUNK];
    int j2 = blockIdx.x * blockDim.x + threadIdx.x;   // bf162 column index
    int r0 = blockIdx.y * CCHUNK;
    if (threadIdx.x < CCHUNK) {
        float M = g_stats[0], invS = g_stats[1];
        xs[threadIdx.x] = expf(t[r0 + threadIdx.x] - M) * invS;
    }
    __syncthreads();
    const __nv_bfloat162* A2 = (const __nv_bfloat162*)A;
    float ax = 0.0f, ay = 0.0f;
#pragma unroll
    for (int r = 0; r < CCHUNK; r++) {
        float2 a = __bfloat1622float2(A2[(size_t)(r0 + r) * (N / 2) + j2]);
        float s = xs[r];
        ax += s * a.x; ay += s * a.y;
    }
    atomicAdd(&y[2 * j2 + 0], ax);
    atomicAdd(&y[2 * j2 + 1], ay);
}

// ---- warp-per-row helpers (streaming loads for single-use matrices) ----
__device__ __forceinline__ float warp_dot_f32_cs(const float* __restrict__ Arow,
                                                 const float* __restrict__ x,
                                                 int lane) {
    const float4* A4 = (const float4*)Arow;
    const float4* x4 = (const float4*)x;
    float acc = 0.0f;
#pragma unroll 8
    for (int i = lane; i < N / 4; i += 32) {
        float4 a = __ldcs(&A4[i]);
        float4 b = __ldg(&x4[i]);
        acc += a.x * b.x + a.y * b.y + a.z * b.z + a.w * b.w;
    }
#pragma unroll
    for (int o = 16; o; o >>= 1) acc += __shfl_down_sync(0xffffffffu, acc, o);
    return acc;
}

__device__ __forceinline__ float warp_dot_bf16_cs(const __nv_bfloat16* __restrict__ Arow,
                                                  const float* __restrict__ x,
                                                  int lane) {
    const uint4* A8 = (const uint4*)Arow;
    const float4* x4 = (const float4*)x;
    float acc = 0.0f;
#pragma unroll 8
    for (int i = lane; i < N / 8; i += 32) {
        uint4 w = __ldcs(&A8[i]);
        float4 x0 = __ldg(&x4[2 * i]);
        float4 x1 = __ldg(&x4[2 * i + 1]);
        float2 f0 = __bfloat1622float2(*(__nv_bfloat162*)&w.x);
        float2 f1 = __bfloat1622float2(*(__nv_bfloat162*)&w.y);
        float2 f2 = __bfloat1622float2(*(__nv_bfloat162*)&w.z);
        float2 f3 = __bfloat1622float2(*(__nv_bfloat162*)&w.w);
        acc += f0.x * x0.x + f0.y * x0.y + f1.x * x0.z + f1.y * x0.w;
        acc += f2.x * x1.x + f2.y * x1.y + f3.x * x1.z + f3.y * x1.w;
    }
#pragma unroll
    for (int o = 16; o; o >>= 1) acc += __shfl_down_sync(0xffffffffu, acc, o);
    return acc;
}

// u = W2 @ sk (fp32 streaming), warp per row, zero t[row]. grid: 512, block: 256
__global__ void k1u_kernel(const float* __restrict__ W2,
                           int step, const int* __restrict__ Kp) {
    if (step >= *Kp) return;
    int lane = threadIdx.x & 31;
    int row = blockIdx.x * 8 + (threadIdx.x >> 5);
    if (lane == 1) g_t[row] = 0.0f;
    float r = warp_dot_f32_cs(W2 + (size_t)row * N, g_sk, lane);
    if (lane == 0) g_u[row] = r;
}

// gh = w_hh @ sk (bf16 streaming), warp per row. grid: G/8 = 1536 (side stream)
__global__ void whh_kernel(int step, const int* __restrict__ Kp) {
    if (step >= *Kp) return;
    int lane = threadIdx.x & 31;
    int row = blockIdx.x * 8 + (threadIdx.x >> 5);
    float r = warp_dot_bf16_cs(g_whh_bf + (size_t)row * N, g_sk, lane);
    if (lane == 0) g_gh[row] = r;
}

// gi = w_ih @ xk (bf16 streaming), warp per row. grid: G/8 = 1536
__global__ void wih_kernel(int step, const int* __restrict__ Kp) {
    if (step >= *Kp) return;
    int lane = threadIdx.x & 31;
    int row = blockIdx.x * 8 + (threadIdx.x >> 5);
    float r = warp_dot_bf16_cs(g_wih_bf + (size_t)row * N, g_xk, lane);
    if (lane == 0) g_gi[row] = r;
}

// softmax stats over t: g_stats = {max, 1/sum}; also zeroes ztgt[0:N].
// single block 1024 threads
__global__ void stats_kernel(const float* __restrict__ t,
                             float* __restrict__ ztgt,
                             int step, const int* __restrict__ Kp) {
    if (step >= *Kp) return;
    int tid = threadIdx.x;
    __shared__ float red[32];

    const float4* t4 = (const float4*)t;
    float vals[4];
    float4 a = t4[tid];
    vals[0] = a.x; vals[1] = a.y; vals[2] = a.z; vals[3] = a.w;
    float m = fmaxf(fmaxf(a.x, a.y), fmaxf(a.z, a.w));
#pragma unroll
    for (int o = 16; o; o >>= 1) m = fmaxf(m, __shfl_down_sync(0xffffffffu, m, o));
    if ((tid & 31) == 0) red[tid >> 5] = m;
    __syncthreads();
    if (tid < 32) {
        float x = red[tid];
#pragma unroll
        for (int o = 16; o; o >>= 1) x = fmaxf(x, __shfl_down_sync(0xffffffffu, x, o));
        if (tid == 0) red[0] = x;
    }
    __syncthreads();
    float M = red[0];
    __syncthreads();

    float s = expf(vals[0] - M) + expf(vals[1] - M) + expf(vals[2] - M) + expf(vals[3] - M);
#pragma unroll
    for (int o = 16; o; o >>= 1) s += __shfl_down_sync(0xffffffffu, s, o);
    if ((tid & 31) == 0) red[tid >> 5] = s;
    __syncthreads();
    if (tid < 32) {
        float x = red[tid];
#pragma unroll
        for (int o = 16; o; o >>= 1) x += __shfl_down_sync(0xffffffffu, x, o);
        if (tid == 0) { g_stats[0] = M; g_stats[1] = 1.0f / x; }
    }

    float4 z = make_float4(0.f, 0.f, 0.f, 0.f);
    ((float4*)ztgt)[tid] = z;
}

// Multi-block GRU elementwise + W3 feature dot -> atomicAdd into g_l3[step].
// grid: 16, block: 256
__global__ void gru_kernel(const float* __restrict__ W3,
                           int step, const int* __restrict__ Kp) {
    if (step >= *Kp) return;
    int i = blockIdx.x * blockDim.x + threadIdx.x;

    float h = g_sk[i];
    float x = g_xk[i];
    float ir = g_gi[i],         hr = g_gh[i];
    float iz = g_gi[N + i],     hz = g_gh[N + i];
    float in = g_gi[2 * N + i], hn = g_gh[2 * N + i];
    float r = 1.0f / (1.0f + expf(-(ir + hr)));
    float z = 1.0f / (1.0f + expf(-(iz + hz)));
    float nn = tanhf(in + r * hn);
    float hnew = (1.0f - z) * nn + z * h;
    g_sk[i] = hnew;

    float ad = fabsf(hnew - x);
    float pr = hnew * x;
    const float* w0 = W3 + (size_t)i * 3;
    const float* w1 = W3 + (size_t)(N + i) * 3;
    const float* w2 = W3 + (size_t)(2 * N + i) * 3;
    const float* w3 = W3 + (size_t)(3 * N + i) * 3;
    float l0 = w0[0] * hnew + w1[0] * x + w2[0] * ad + w3[0] * pr;
    float l1 = w0[1] * hnew + w1[1] * x + w2[1] * ad + w3[1] * pr;
    float l2 = w0[2] * hnew + w1[2] * x + w2[2] * ad + w3[2] * pr;
#pragma unroll
    for (int o = 16; o; o >>= 1) {
        l0 += __shfl_down_sync(0xffffffffu, l0, o);
        l1 += __shfl_down_sync(0xffffffffu, l1, o);
        l2 += __shfl_down_sync(0xffffffffu, l2, o);
    }
    if ((threadIdx.x & 31) == 0) {
        atomicAdd(&g_l3[step * 3 + 0], l0);
        atomicAdd(&g_l3[step * 3 + 1], l1);
        atomicAdd(&g_l3[step * 3 + 2], l2);
    }
}

// per-step label softmax + average (K steps, K <= 8; unused steps are zero)
__global__ void final_kernel(float* __restrict__ out, const int* __restrict__ Kp) {
    if (threadIdx.x == 0) {
        int K = *Kp;
        float p0 = 0.f, p1 = 0.f, p2 = 0.f;
        for (int s = 0; s < K; s++) {
            float a = g_l3[s * 3 + 0], b = g_l3[s * 3 + 1], c = g_l3[s * 3 + 2];
            float m = fmaxf(a, fmaxf(b, c));
            float ea = expf(a - m), eb = expf(b - m), ec = expf(c - m);
            float sum = ea + eb + ec;
            p0 += ea / sum; p1 += eb / sum; p2 += ec / sum;
        }
        out[0] = p0 / (float)K;
        out[1] = p1 / (float)K;
        out[2] = p2 / (float)K;
    }
}

// ---------------- host launch ----------------
static cudaStream_t h_s2 = nullptr;
static cudaEvent_t h_evF = nullptr;   // fork (start -> s2)
static cudaEvent_t h_evB = nullptr;   // wih conversion done (s2 -> main)
static cudaEvent_t h_evM = nullptr;   // mp conversion done (s2 -> main)
static cudaEvent_t h_evS = nullptr;   // sk ready (main -> s2)
static cudaEvent_t h_evG = nullptr;   // gh ready (s2 -> main)
static bool h_tried = false;

extern "C" void kernel_launch(void* const* d_in, const int* in_sizes, int n_in,
                              void* d_out, int out_size) {
    const float* M_h   = (const float*)d_in[0];
    const float* M_p   = (const float*)d_in[1];
    const float* w1    = (const float*)d_in[2];
    const float* W2    = (const float*)d_in[3];
    const float* W3    = (const float*)d_in[4];
    const float* w_ih  = (const float*)d_in[5];
    const float* w_hh  = (const float*)d_in[6];
    const int*   Kp    = (const int*)d_in[7];
    float* out = (float*)d_out;

    float *t, *sk, *u, *xk;
    __nv_bfloat16 *wih_bf, *whh_bf, *mp_bf;
    cudaGetSymbolAddress((void**)&t,      g_t);
    cudaGetSymbolAddress((void**)&sk,     g_sk);
    cudaGetSymbolAddress((void**)&u,      g_u);
    cudaGetSymbolAddress((void**)&xk,     g_xk);
    cudaGetSymbolAddress((void**)&wih_bf, g_wih_bf);
    cudaGetSymbolAddress((void**)&whh_bf, g_whh_bf);
    cudaGetSymbolAddress((void**)&mp_bf,  g_mp_bf);

    if (!h_tried) {
        h_tried = true;
        if (cudaStreamCreateWithFlags(&h_s2, cudaStreamNonBlocking) == cudaSuccess) {
            cudaEventCreateWithFlags(&h_evF, cudaEventDisableTiming);
            cudaEventCreateWithFlags(&h_evB, cudaEventDisableTiming);
            cudaEventCreateWithFlags(&h_evM, cudaEventDisableTiming);
            cudaEventCreateWithFlags(&h_evS, cudaEventDisableTiming);
            cudaEventCreateWithFlags(&h_evG, cudaEventDisableTiming);
        } else {
            h_s2 = nullptr;
        }
    }
    const bool dual = (h_s2 != nullptr);
    cudaStream_t s2 = dual ? h_s2 : (cudaStream_t)0;

    dim3 cgrid(N / 256, N / CCHUNK);    // fp32 colmv: (16, 128)
    dim3 cgrid2(N / 512, N / CCHUNK);   // bf16 colmv_exp: (8, 128)
    const int n8g = G * (N / 8);        // gate matrices
    const int n8n = N * (N / 8);        // M_p

    // ---- fork: conversions on s2 (wih -> mp -> whh; whh ordered in-stream
    // before the first whh_kernel so main never waits on it) ----
    init_kernel<<<(N + 1023) / 1024, 1024>>>();
    if (dual) {
        cudaEventRecord(h_evF, 0);
        cudaStreamWaitEvent(s2, h_evF, 0);
    }
    convert_bf16_kernel<<<(n8g + 255) / 256, 256, 0, s2>>>(w_ih, wih_bf, n8g);
    if (dual) cudaEventRecord(h_evB, s2);
    convert_bf16_kernel<<<(n8n + 255) / 256, 256, 0, s2>>>(M_p, mp_bf, n8n);
    if (dual) cudaEventRecord(h_evM, s2);
    convert_bf16_kernel<<<(n8g + 255) / 256, 256, 0, s2>>>(w_hh, whh_bf, n8g);

    // prologue: alpha logits -> stats -> sk0 = softmax(alpha) @ M_h (fp32)
    colmv_kernel<<<cgrid, 256>>>(M_h, w1, t, 0, Kp);
    stats_kernel<<<1, 1024>>>(t, sk, 0, Kp);
    colmv_exp_kernel<<<cgrid, 256>>>(M_h, t, sk, 0, Kp);
    if (dual) cudaEventRecord(h_evS, 0);   // sk ready

    const int MAX_STEPS = 8;
    for (int s = 0; s < MAX_STEPS; s++) {
        // side stream: gh = w_hh @ sk (whh conversion precedes in-stream)
        if (dual) cudaStreamWaitEvent(s2, h_evS, 0);
        whh_kernel<<<G / 8, 256, 0, s2>>>(s, Kp);
        if (dual) cudaEventRecord(h_evG, s2);

        // main: beta chain
        k1u_kernel<<<N / 8, 256>>>(W2, s, Kp);                 // u = W2@sk, zero t
        colmv_kernel<<<cgrid, 256>>>(M_p, u, t, s, Kp);        // logits (fp32 M_p, L2-resident)
        stats_kernel<<<1, 1024>>>(t, xk, s, Kp);               // M, 1/S; zero xk
        if (dual && s == 0) cudaStreamWaitEvent(0, h_evM, 0);  // need mp_bf now
        colmv_exp_bf16_kernel<<<cgrid2, 256>>>(mp_bf, t, xk, s, Kp); // xk = beta @ M_p (bf16)
        if (dual && s == 0) cudaStreamWaitEvent(0, h_evB, 0);  // need wih_bf now
        wih_kernel<<<G / 8, 256>>>(s, Kp);                     // gi = w_ih @ xk

        if (dual) cudaStreamWaitEvent(0, h_evG, 0);            // join gh
        gru_kernel<<<16, 256>>>(W3, s, Kp);                    // sk update + l3[s]
        if (dual) cudaEventRecord(h_evS, 0);                   // sk ready for next whh
    }

    final_kernel<<<1, 32>>>(out, Kp);
}

// round 16
// speedup vs baseline: 1.0787x; 1.0787x over previous
#include <cuda_runtime.h>
#include <cuda_bf16.h>
#include <math.h>

#define N 4096
#define G (3 * N)
#define CCHUNK 32          // rows per colmv block -> grid (16,128) = 2048 blocks

// ---------------- device scratch ----------------
__device__ float g_t[N];        // logits buffer
__device__ float g_sk[N];       // GRU hidden state
__device__ float g_u[N];        // u = W2 @ sk
__device__ float g_xk[N];       // x_k
__device__ float g_gi[G];       // w_ih @ xk
__device__ float g_gh[G];       // w_hh @ sk
__device__ float g_stats[2];    // [max, 1/sum] of current logits
__device__ float g_l3[8 * 3];   // per-step label logits (atomically accumulated)

// bf16 copies of the GRU weights (gates only: safe behind sigmoid/tanh;
// logits/recurrence path stays fp32 — R12 and R15 both proved it must)
__device__ __nv_bfloat16 g_wih_bf[(size_t)G * N];   // 96 MB
__device__ __nv_bfloat16 g_whh_bf[(size_t)G * N];   // 96 MB

// ---------------- kernels ----------------

// zero g_t and g_l3 (runs at the start of every call/replay)
__global__ void init_kernel() {
    int i = blockIdx.x * blockDim.x + threadIdx.x;
    if (i < N) g_t[i] = 0.0f;
    if (i < 24) g_l3[i] = 0.0f;
}

// fp32 -> bf16 conversion, 8 elements/thread. Streaming loads+stores (evict-first)
// so the conversion doesn't evict L2-resident M_p.
__global__ void convert_bf16_kernel(const float* __restrict__ src,
                                    __nv_bfloat16* __restrict__ dst,
                                    int n8) {
    int idx = blockIdx.x * blockDim.x + threadIdx.x;
    if (idx >= n8) return;
    const float4* s4 = (const float4*)src;
    float4 a = __ldcs(&s4[2 * idx]);
    float4 b = __ldcs(&s4[2 * idx + 1]);
    __nv_bfloat162 p0 = __floats2bfloat162_rn(a.x, a.y);
    __nv_bfloat162 p1 = __floats2bfloat162_rn(a.z, a.w);
    __nv_bfloat162 p2 = __floats2bfloat162_rn(b.x, b.y);
    __nv_bfloat162 p3 = __floats2bfloat162_rn(b.z, b.w);
    uint4 out;
    out.x = *(unsigned int*)&p0;
    out.y = *(unsigned int*)&p1;
    out.z = *(unsigned int*)&p2;
    out.w = *(unsigned int*)&p3;
    __stcs((uint4*)dst + idx, out);
}

// y[j] += sum_r x[r] * A[r, j]   (fp32; default caching -> A stays L2-resident)
// grid: (16, 128) = 2048 blocks, block: 256
__global__ void colmv_kernel(const float* __restrict__ A,
                             const float* __restrict__ x,
                             float* __restrict__ y,
                             int step, const int* __restrict__ Kp) {
    if (step >= *Kp) return;
    __shared__ float xs[CCHUNK];
    int j = blockIdx.x * blockDim.x + threadIdx.x;
    int r0 = blockIdx.y * CCHUNK;
    if (threadIdx.x < CCHUNK) xs[threadIdx.x] = x[r0 + threadIdx.x];
    __syncthreads();
    const float* Ap = A + (size_t)r0 * N + j;
    float acc = 0.0f;
#pragma unroll
    for (int r = 0; r < CCHUNK; r++)
        acc += xs[r] * Ap[(size_t)r * N];
    atomicAdd(&y[j], acc);
}

// y[j] += sum_r (exp(t[r]-M)*invS) * A[r, j]   (softmax weights from g_stats)
__global__ void colmv_exp_kernel(const float* __restrict__ A,
                                 const float* __restrict__ t,
                                 float* __restrict__ y,
                                 int step, const int* __restrict__ Kp) {
    if (step >= *Kp) return;
    __shared__ float xs[CCHUNK];
    int j = blockIdx.x * blockDim.x + threadIdx.x;
    int r0 = blockIdx.y * CCHUNK;
    if (threadIdx.x < CCHUNK) {
        float M = g_stats[0], invS = g_stats[1];
        xs[threadIdx.x] = expf(t[r0 + threadIdx.x] - M) * invS;
    }
    __syncthreads();
    const float* Ap = A + (size_t)r0 * N + j;
    float acc = 0.0f;
#pragma unroll
    for (int r = 0; r < CCHUNK; r++)
        acc += xs[r] * Ap[(size_t)r * N];
    atomicAdd(&y[j], acc);
}

// ---- warp-per-row helpers (STREAMING loads: read-once matrices must not
// evict L2-resident M_p) ----
__device__ __forceinline__ float warp_dot_f32_cs(const float* __restrict__ Arow,
                                                 const float* __restrict__ x,
                                                 int lane) {
    const float4* A4 = (const float4*)Arow;
    const float4* x4 = (const float4*)x;
    float acc = 0.0f;
#pragma unroll 8
    for (int i = lane; i < N / 4; i += 32) {
        float4 a = __ldcs(&A4[i]);
        float4 b = __ldg(&x4[i]);
        acc += a.x * b.x + a.y * b.y + a.z * b.z + a.w * b.w;
    }
#pragma unroll
    for (int o = 16; o; o >>= 1) acc += __shfl_down_sync(0xffffffffu, acc, o);
    return acc;
}

__device__ __forceinline__ float warp_dot_bf16_cs(const __nv_bfloat16* __restrict__ Arow,
                                                  const float* __restrict__ x,
                                                  int lane) {
    const uint4* A8 = (const uint4*)Arow;
    const float4* x4 = (const float4*)x;
    float acc = 0.0f;
#pragma unroll 8
    for (int i = lane; i < N / 8; i += 32) {
        uint4 w = __ldcs(&A8[i]);
        float4 x0 = __ldg(&x4[2 * i]);
        float4 x1 = __ldg(&x4[2 * i + 1]);
        float2 f0 = __bfloat1622float2(*(__nv_bfloat162*)&w.x);
        float2 f1 = __bfloat1622float2(*(__nv_bfloat162*)&w.y);
        float2 f2 = __bfloat1622float2(*(__nv_bfloat162*)&w.z);
        float2 f3 = __bfloat1622float2(*(__nv_bfloat162*)&w.w);
        acc += f0.x * x0.x + f0.y * x0.y + f1.x * x0.z + f1.y * x0.w;
        acc += f2.x * x1.x + f2.y * x1.y + f3.x * x1.z + f3.y * x1.w;
    }
#pragma unroll
    for (int o = 16; o; o >>= 1) acc += __shfl_down_sync(0xffffffffu, acc, o);
    return acc;
}

// u = W2 @ sk (fp32 streaming), warp per row, zero t[row]. grid: 512, block: 256
__global__ void k1u_kernel(const float* __restrict__ W2,
                           int step, const int* __restrict__ Kp) {
    if (step >= *Kp) return;
    int lane = threadIdx.x & 31;
    int row = blockIdx.x * 8 + (threadIdx.x >> 5);
    if (lane == 1) g_t[row] = 0.0f;
    float r = warp_dot_f32_cs(W2 + (size_t)row * N, g_sk, lane);
    if (lane == 0) g_u[row] = r;
}

// gh = w_hh @ sk (bf16 streaming), warp per row. grid: G/8 = 1536 (side stream)
__global__ void whh_kernel(int step, const int* __restrict__ Kp) {
    if (step >= *Kp) return;
    int lane = threadIdx.x & 31;
    int row = blockIdx.x * 8 + (threadIdx.x >> 5);
    float r = warp_dot_bf16_cs(g_whh_bf + (size_t)row * N, g_sk, lane);
    if (lane == 0) g_gh[row] = r;
}

// gi = w_ih @ xk (bf16 streaming), warp per row. grid: G/8 = 1536
__global__ void wih_kernel(int step, const int* __restrict__ Kp) {
    if (step >= *Kp) return;
    int lane = threadIdx.x & 31;
    int row = blockIdx.x * 8 + (threadIdx.x >> 5);
    float r = warp_dot_bf16_cs(g_wih_bf + (size_t)row * N, g_xk, lane);
    if (lane == 0) g_gi[row] = r;
}

// softmax stats over t: g_stats = {max, 1/sum}; also zeroes ztgt[0:N].
// single block 1024 threads
__global__ void stats_kernel(const float* __restrict__ t,
                             float* __restrict__ ztgt,
                             int step, const int* __restrict__ Kp) {
    if (step >= *Kp) return;
    int tid = threadIdx.x;
    __shared__ float red[32];

    const float4* t4 = (const float4*)t;
    float vals[4];
    float4 a = t4[tid];                 // 1024 float4, one per thread
    vals[0] = a.x; vals[1] = a.y; vals[2] = a.z; vals[3] = a.w;
    float m = fmaxf(fmaxf(a.x, a.y), fmaxf(a.z, a.w));
#pragma unroll
    for (int o = 16; o; o >>= 1) m = fmaxf(m, __shfl_down_sync(0xffffffffu, m, o));
    if ((tid & 31) == 0) red[tid >> 5] = m;
    __syncthreads();
    if (tid < 32) {
        float x = red[tid];
#pragma unroll
        for (int o = 16; o; o >>= 1) x = fmaxf(x, __shfl_down_sync(0xffffffffu, x, o));
        if (tid == 0) red[0] = x;
    }
    __syncthreads();
    float M = red[0];
    __syncthreads();

    float s = expf(vals[0] - M) + expf(vals[1] - M) + expf(vals[2] - M) + expf(vals[3] - M);
#pragma unroll
    for (int o = 16; o; o >>= 1) s += __shfl_down_sync(0xffffffffu, s, o);
    if ((tid & 31) == 0) red[tid >> 5] = s;
    __syncthreads();
    if (tid < 32) {
        float x = red[tid];
#pragma unroll
        for (int o = 16; o; o >>= 1) x += __shfl_down_sync(0xffffffffu, x, o);
        if (tid == 0) { g_stats[0] = M; g_stats[1] = 1.0f / x; }
    }

    float4 z = make_float4(0.f, 0.f, 0.f, 0.f);
    ((float4*)ztgt)[tid] = z;
}

// Multi-block GRU elementwise + W3 feature dot -> atomicAdd into g_l3[step].
// grid: 16, block: 256 (one thread per hidden element)
__global__ void gru_kernel(const float* __restrict__ W3,
                           int step, const int* __restrict__ Kp) {
    if (step >= *Kp) return;
    int i = blockIdx.x * blockDim.x + threadIdx.x;

    float h = g_sk[i];
    float x = g_xk[i];
    float ir = g_gi[i],         hr = g_gh[i];
    float iz = g_gi[N + i],     hz = g_gh[N + i];
    float in = g_gi[2 * N + i], hn = g_gh[2 * N + i];
    float r = 1.0f / (1.0f + expf(-(ir + hr)));
    float z = 1.0f / (1.0f + expf(-(iz + hz)));
    float nn = tanhf(in + r * hn);
    float hnew = (1.0f - z) * nn + z * h;
    g_sk[i] = hnew;

    float ad = fabsf(hnew - x);
    float pr = hnew * x;
    const float* w0 = W3 + (size_t)i * 3;
    const float* w1 = W3 + (size_t)(N + i) * 3;
    const float* w2 = W3 + (size_t)(2 * N + i) * 3;
    const float* w3 = W3 + (size_t)(3 * N + i) * 3;
    float l0 = w0[0] * hnew + w1[0] * x + w2[0] * ad + w3[0] * pr;
    float l1 = w0[1] * hnew + w1[1] * x + w2[1] * ad + w3[1] * pr;
    float l2 = w0[2] * hnew + w1[2] * x + w2[2] * ad + w3[2] * pr;
#pragma unroll
    for (int o = 16; o; o >>= 1) {
        l0 += __shfl_down_sync(0xffffffffu, l0, o);
        l1 += __shfl_down_sync(0xffffffffu, l1, o);
        l2 += __shfl_down_sync(0xffffffffu, l2, o);
    }
    if ((threadIdx.x & 31) == 0) {
        atomicAdd(&g_l3[step * 3 + 0], l0);
        atomicAdd(&g_l3[step * 3 + 1], l1);
        atomicAdd(&g_l3[step * 3 + 2], l2);
    }
}

// per-step label softmax + average (K steps, K <= 8; unused steps are zero)
__global__ void final_kernel(float* __restrict__ out, const int* __restrict__ Kp) {
    if (threadIdx.x == 0) {
        int K = *Kp;
        float p0 = 0.f, p1 = 0.f, p2 = 0.f;
        for (int s = 0; s < K; s++) {
            float a = g_l3[s * 3 + 0], b = g_l3[s * 3 + 1], c = g_l3[s * 3 + 2];
            float m = fmaxf(a, fmaxf(b, c));
            float ea = expf(a - m), eb = expf(b - m), ec = expf(c - m);
            float sum = ea + eb + ec;
            p0 += ea / sum; p1 += eb / sum; p2 += ec / sum;
        }
        out[0] = p0 / (float)K;
        out[1] = p1 / (float)K;
        out[2] = p2 / (float)K;
    }
}

// ---------------- host launch ----------------
static cudaStream_t h_s2 = nullptr;
static cudaEvent_t h_evF = nullptr;   // fork (start -> s2)
static cudaEvent_t h_evB = nullptr;   // wih conversion done (s2 -> main)
static cudaEvent_t h_evS = nullptr;   // sk ready (main -> s2)
static cudaEvent_t h_evG = nullptr;   // gh ready (s2 -> main)
static bool h_tried = false;

extern "C" void kernel_launch(void* const* d_in, const int* in_sizes, int n_in,
                              void* d_out, int out_size) {
    const float* M_h   = (const float*)d_in[0];
    const float* M_p   = (const float*)d_in[1];
    const float* w1    = (const float*)d_in[2];
    const float* W2    = (const float*)d_in[3];
    const float* W3    = (const float*)d_in[4];
    const float* w_ih  = (const float*)d_in[5];
    const float* w_hh  = (const float*)d_in[6];
    const int*   Kp    = (const int*)d_in[7];
    float* out = (float*)d_out;

    float *t, *sk, *u, *xk;
    __nv_bfloat16 *wih_bf, *whh_bf;
    cudaGetSymbolAddress((void**)&t,      g_t);
    cudaGetSymbolAddress((void**)&sk,     g_sk);
    cudaGetSymbolAddress((void**)&u,      g_u);
    cudaGetSymbolAddress((void**)&xk,     g_xk);
    cudaGetSymbolAddress((void**)&wih_bf, g_wih_bf);
    cudaGetSymbolAddress((void**)&whh_bf, g_whh_bf);

    if (!h_tried) {
        h_tried = true;
        if (cudaStreamCreateWithFlags(&h_s2, cudaStreamNonBlocking) == cudaSuccess) {
            cudaEventCreateWithFlags(&h_evF, cudaEventDisableTiming);
            cudaEventCreateWithFlags(&h_evB, cudaEventDisableTiming);
            cudaEventCreateWithFlags(&h_evS, cudaEventDisableTiming);
            cudaEventCreateWithFlags(&h_evG, cudaEventDisableTiming);
        } else {
            h_s2 = nullptr;
        }
    }
    const bool dual = (h_s2 != nullptr);
    cudaStream_t s2 = dual ? h_s2 : (cudaStream_t)0;

    dim3 cgrid(N / 256, N / CCHUNK);   // (16, 128) = 2048 blocks
    const int n8 = G * (N / 8);

    // ---- fork: conversions on s2 (wih first; whh ordered in-stream) ----
    init_kernel<<<(N + 1023) / 1024, 1024>>>();
    if (dual) {
        cudaEventRecord(h_evF, 0);
        cudaStreamWaitEvent(s2, h_evF, 0);
    }
    convert_bf16_kernel<<<(n8 + 255) / 256, 256, 0, s2>>>(w_ih, wih_bf, n8);
    if (dual) cudaEventRecord(h_evB, s2);
    convert_bf16_kernel<<<(n8 + 255) / 256, 256, 0, s2>>>(w_hh, whh_bf, n8);

    // prologue: alpha logits -> stats -> sk0 = softmax(alpha) @ M_h
    colmv_kernel<<<cgrid, 256>>>(M_h, w1, t, 0, Kp);
    stats_kernel<<<1, 1024>>>(t, sk, 0, Kp);
    colmv_exp_kernel<<<cgrid, 256>>>(M_h, t, sk, 0, Kp);
    if (dual) cudaEventRecord(h_evS, 0);   // sk ready

    const int MAX_STEPS = 8;
    for (int s = 0; s < MAX_STEPS; s++) {
        // side stream: gh = w_hh @ sk (whh conversion precedes in-stream)
        if (dual) cudaStreamWaitEvent(s2, h_evS, 0);
        whh_kernel<<<G / 8, 256, 0, s2>>>(s, Kp);
        if (dual) cudaEventRecord(h_evG, s2);

        // main: beta chain
        k1u_kernel<<<N / 8, 256>>>(W2, s, Kp);                 // u = W2@sk, zero t
        colmv_kernel<<<cgrid, 256>>>(M_p, u, t, s, Kp);        // logits (M_p cached)
        stats_kernel<<<1, 1024>>>(t, xk, s, Kp);               // M, 1/S; zero xk
        colmv_exp_kernel<<<cgrid, 256>>>(M_p, t, xk, s, Kp);   // xk = beta @ M_p
        if (dual && s == 0) cudaStreamWaitEvent(0, h_evB, 0);  // need wih_bf now
        wih_kernel<<<G / 8, 256>>>(s, Kp);                     // gi = w_ih @ xk

        if (dual) cudaStreamWaitEvent(0, h_evG, 0);            // join gh
        gru_kernel<<<16, 256>>>(W3, s, Kp);                    // sk update + l3[s]
        if (dual) cudaEventRecord(h_evS, 0);                   // sk ready for next whh
    }

    final_kernel<<<1, 32>>>(out, Kp);
}

// round 17
// speedup vs baseline: 1.1503x; 1.0664x over previous
#include <cuda_runtime.h>
#include <cuda_fp16.h>
#include <math.h>

#define N 4096
#define G (3 * N)
#define CCHUNK 32

// ---------------- device scratch ----------------
__device__ float g_t[N];        // logits buffer
__device__ float g_sk[N];       // GRU hidden state
__device__ float g_u[N];        // u = W2 @ sk
__device__ float g_xk[N];       // x_k
__device__ float g_gi[G];       // w_ih @ xk
__device__ float g_gh[G];       // w_hh @ sk
__device__ float g_stats[2];    // [max, 1/sum] of current logits
__device__ float g_l3[8 * 3];   // per-step label logits

// fp16 copies (11-bit significand: 8x less quantization error than bf16;
// measured R12/R15 bf16 errors scaled by 1/8 predict ~3.5e-4 total)
__device__ __half g_wih_h[(size_t)G * N];   // 96 MB, streamed
__device__ __half g_whh_h[(size_t)G * N];   // 96 MB, streamed
__device__ __half g_w2_h[(size_t)N * N];    // 32 MB, L2-resident (8 reads)
__device__ __half g_mp_h[(size_t)N * N];    // 32 MB, L2-resident (16 reads)

// ---------------- kernels ----------------

__global__ void init_kernel() {
    int i = blockIdx.x * blockDim.x + threadIdx.x;
    if (i < N) g_t[i] = 0.0f;
    if (i < 24) g_l3[i] = 0.0f;
}

// fp32 -> fp16, 8 elems/thread. Streaming src loads; dst stores default-cached
// (resident=1: W2/M_p copies should LAND in L2) or streaming (resident=0: gates).
__global__ void convert_fp16_kernel(const float* __restrict__ src,
                                    __half* __restrict__ dst,
                                    int n8, int resident) {
    int idx = blockIdx.x * blockDim.x + threadIdx.x;
    if (idx >= n8) return;
    const float4* s4 = (const float4*)src;
    float4 a = __ldcs(&s4[2 * idx]);
    float4 b = __ldcs(&s4[2 * idx + 1]);
    __half2 p0 = __floats2half2_rn(a.x, a.y);
    __half2 p1 = __floats2half2_rn(a.z, a.w);
    __half2 p2 = __floats2half2_rn(b.x, b.y);
    __half2 p3 = __floats2half2_rn(b.z, b.w);
    uint4 out;
    out.x = *(unsigned int*)&p0;
    out.y = *(unsigned int*)&p1;
    out.z = *(unsigned int*)&p2;
    out.w = *(unsigned int*)&p3;
    if (resident) ((uint4*)dst)[idx] = out;
    else          __stcs((uint4*)dst + idx, out);
}

// fp32 colmv (prologue M_h only): y[j] += sum_r x[r] * A[r, j]
// grid: (16, 128) = 2048 blocks, block: 256
__global__ void colmv_kernel(const float* __restrict__ A,
                             const float* __restrict__ x,
                             float* __restrict__ y,
                             int step, const int* __restrict__ Kp) {
    if (step >= *Kp) return;
    __shared__ float xs[CCHUNK];
    int j = blockIdx.x * blockDim.x + threadIdx.x;
    int r0 = blockIdx.y * CCHUNK;
    if (threadIdx.x < CCHUNK) xs[threadIdx.x] = x[r0 + threadIdx.x];
    __syncthreads();
    const float* Ap = A + (size_t)r0 * N + j;
    float acc = 0.0f;
#pragma unroll
    for (int r = 0; r < CCHUNK; r++)
        acc += xs[r] * Ap[(size_t)r * N];
    atomicAdd(&y[j], acc);
}

// fp32 colmv_exp (prologue M_h only)
__global__ void colmv_exp_kernel(const float* __restrict__ A,
                                 const float* __restrict__ t,
                                 float* __restrict__ y,
                                 int step, const int* __restrict__ Kp) {
    if (step >= *Kp) return;
    __shared__ float xs[CCHUNK];
    int j = blockIdx.x * blockDim.x + threadIdx.x;
    int r0 = blockIdx.y * CCHUNK;
    if (threadIdx.x < CCHUNK) {
        float M = g_stats[0], invS = g_stats[1];
        xs[threadIdx.x] = expf(t[r0 + threadIdx.x] - M) * invS;
    }
    __syncthreads();
    const float* Ap = A + (size_t)r0 * N + j;
    float acc = 0.0f;
#pragma unroll
    for (int r = 0; r < CCHUNK; r++)
        acc += xs[r] * Ap[(size_t)r * N];
    atomicAdd(&y[j], acc);
}

// fp16 colmv: y[2j..2j+1] += sum_r x[r] * A_h[r, 2j..2j+1]. Default-cached:
// mp_h must stay L2-resident. grid: (8, 128) = 1024 blocks, block: 256
__global__ void colmv_fp16_kernel(const __half* __restrict__ A,
                                  const float* __restrict__ x,
                                  float* __restrict__ y,
                                  int step, const int* __restrict__ Kp) {
    if (step >= *Kp) return;
    __shared__ float xs[CCHUNK];
    int j2 = blockIdx.x * blockDim.x + threadIdx.x;
    int r0 = blockIdx.y * CCHUNK;
    if (threadIdx.x < CCHUNK) xs[threadIdx.x] = x[r0 + threadIdx.x];
    __syncthreads();
    const __half2* A2 = (const __half2*)A;
    float ax = 0.0f, ay = 0.0f;
#pragma unroll
    for (int r = 0; r < CCHUNK; r++) {
        float2 a = __half22float2(A2[(size_t)(r0 + r) * (N / 2) + j2]);
        float s = xs[r];
        ax += s * a.x; ay += s * a.y;
    }
    atomicAdd(&y[2 * j2 + 0], ax);
    atomicAdd(&y[2 * j2 + 1], ay);
}

// fp16 colmv_exp (xk pass): softmax weights from g_stats
__global__ void colmv_exp_fp16_kernel(const __half* __restrict__ A,
                                      const float* __restrict__ t,
                                      float* __restrict__ y,
                                      int step, const int* __restrict__ Kp) {
    if (step >= *Kp) return;
    __shared__ float xs[CCHUNK];
    int j2 = blockIdx.x * blockDim.x + threadIdx.x;
    int r0 = blockIdx.y * CCHUNK;
    if (threadIdx.x < CCHUNK) {
        float M = g_stats[0], invS = g_stats[1];
        xs[threadIdx.x] = expf(t[r0 + threadIdx.x] - M) * invS;
    }
    __syncthreads();
    const __half2* A2 = (const __half2*)A;
    float ax = 0.0f, ay = 0.0f;
#pragma unroll
    for (int r = 0; r < CCHUNK; r++) {
        float2 a = __half22float2(A2[(size_t)(r0 + r) * (N / 2) + j2]);
        float s = xs[r];
        ax += s * a.x; ay += s * a.y;
    }
    atomicAdd(&y[2 * j2 + 0], ax);
    atomicAdd(&y[2 * j2 + 1], ay);
}

// ---- warp-per-row fp16 dots ----
// cached variant (W2: reused across steps, keep in L2)
__device__ __forceinline__ float warp_dot_h(const __half* __restrict__ Arow,
                                            const float* __restrict__ x,
                                            int lane) {
    const uint4* A8 = (const uint4*)Arow;
    const float4* x4 = (const float4*)x;
    float acc = 0.0f;
#pragma unroll 8
    for (int i = lane; i < N / 8; i += 32) {
        uint4 w = __ldg(&A8[i]);
        float4 x0 = __ldg(&x4[2 * i]);
        float4 x1 = __ldg(&x4[2 * i + 1]);
        float2 f0 = __half22float2(*(__half2*)&w.x);
        float2 f1 = __half22float2(*(__half2*)&w.y);
        float2 f2 = __half22float2(*(__half2*)&w.z);
        float2 f3 = __half22float2(*(__half2*)&w.w);
        acc += f0.x * x0.x + f0.y * x0.y + f1.x * x0.z + f1.y * x0.w;
        acc += f2.x * x1.x + f2.y * x1.y + f3.x * x1.z + f3.y * x1.w;
    }
#pragma unroll
    for (int o = 16; o; o >>= 1) acc += __shfl_down_sync(0xffffffffu, acc, o);
    return acc;
}

// streaming variant (gate matrices: single use per step, don't evict L2 set)
__device__ __forceinline__ float warp_dot_h_cs(const __half* __restrict__ Arow,
                                               const float* __restrict__ x,
                                               int lane) {
    const uint4* A8 = (const uint4*)Arow;
    const float4* x4 = (const float4*)x;
    float acc = 0.0f;
#pragma unroll 8
    for (int i = lane; i < N / 8; i += 32) {
        uint4 w = __ldcs(&A8[i]);
        float4 x0 = __ldg(&x4[2 * i]);
        float4 x1 = __ldg(&x4[2 * i + 1]);
        float2 f0 = __half22float2(*(__half2*)&w.x);
        float2 f1 = __half22float2(*(__half2*)&w.y);
        float2 f2 = __half22float2(*(__half2*)&w.z);
        float2 f3 = __half22float2(*(__half2*)&w.w);
        acc += f0.x * x0.x + f0.y * x0.y + f1.x * x0.z + f1.y * x0.w;
        acc += f2.x * x1.x + f2.y * x1.y + f3.x * x1.z + f3.y * x1.w;
    }
#pragma unroll
    for (int o = 16; o; o >>= 1) acc += __shfl_down_sync(0xffffffffu, acc, o);
    return acc;
}

// u = W2_h @ sk (cached: W2_h L2-resident), warp per row, zero t[row].
// grid: N/8 = 512, block: 256
__global__ void k1u_kernel(int step, const int* __restrict__ Kp) {
    if (step >= *Kp) return;
    int lane = threadIdx.x & 31;
    int row = blockIdx.x * 8 + (threadIdx.x >> 5);
    if (lane == 1) g_t[row] = 0.0f;
    float r = warp_dot_h(g_w2_h + (size_t)row * N, g_sk, lane);
    if (lane == 0) g_u[row] = r;
}

// gh = w_hh_h @ sk (streaming), warp per row. grid: G/8 = 1536 (side stream)
__global__ void whh_kernel(int step, const int* __restrict__ Kp) {
    if (step >= *Kp) return;
    int lane = threadIdx.x & 31;
    int row = blockIdx.x * 8 + (threadIdx.x >> 5);
    float r = warp_dot_h_cs(g_whh_h + (size_t)row * N, g_sk, lane);
    if (lane == 0) g_gh[row] = r;
}

// gi = w_ih_h @ xk (streaming), warp per row. grid: G/8 = 1536
__global__ void wih_kernel(int step, const int* __restrict__ Kp) {
    if (step >= *Kp) return;
    int lane = threadIdx.x & 31;
    int row = blockIdx.x * 8 + (threadIdx.x >> 5);
    float r = warp_dot_h_cs(g_wih_h + (size_t)row * N, g_xk, lane);
    if (lane == 0) g_gi[row] = r;
}

// softmax stats over t: g_stats = {max, 1/sum}; also zeroes ztgt[0:N].
// single block 1024 threads
__global__ void stats_kernel(const float* __restrict__ t,
                             float* __restrict__ ztgt,
                             int step, const int* __restrict__ Kp) {
    if (step >= *Kp) return;
    int tid = threadIdx.x;
    __shared__ float red[32];

    const float4* t4 = (const float4*)t;
    float vals[4];
    float4 a = t4[tid];
    vals[0] = a.x; vals[1] = a.y; vals[2] = a.z; vals[3] = a.w;
    float m = fmaxf(fmaxf(a.x, a.y), fmaxf(a.z, a.w));
#pragma unroll
    for (int o = 16; o; o >>= 1) m = fmaxf(m, __shfl_down_sync(0xffffffffu, m, o));
    if ((tid & 31) == 0) red[tid >> 5] = m;
    __syncthreads();
    if (tid < 32) {
        float x = red[tid];
#pragma unroll
        for (int o = 16; o; o >>= 1) x = fmaxf(x, __shfl_down_sync(0xffffffffu, x, o));
        if (tid == 0) red[0] = x;
    }
    __syncthreads();
    float M = red[0];
    __syncthreads();

    float s = expf(vals[0] - M) + expf(vals[1] - M) + expf(vals[2] - M) + expf(vals[3] - M);
#pragma unroll
    for (int o = 16; o; o >>= 1) s += __shfl_down_sync(0xffffffffu, s, o);
    if ((tid & 31) == 0) red[tid >> 5] = s;
    __syncthreads();
    if (tid < 32) {
        float x = red[tid];
#pragma unroll
        for (int o = 16; o; o >>= 1) x += __shfl_down_sync(0xffffffffu, x, o);
        if (tid == 0) { g_stats[0] = M; g_stats[1] = 1.0f / x; }
    }

    float4 z = make_float4(0.f, 0.f, 0.f, 0.f);
    ((float4*)ztgt)[tid] = z;
}

// Multi-block GRU elementwise + W3 feature dot -> atomicAdd into g_l3[step].
// grid: 16, block: 256
__global__ void gru_kernel(const float* __restrict__ W3,
                           int step, const int* __restrict__ Kp) {
    if (step >= *Kp) return;
    int i = blockIdx.x * blockDim.x + threadIdx.x;

    float h = g_sk[i];
    float x = g_xk[i];
    float ir = g_gi[i],         hr = g_gh[i];
    float iz = g_gi[N + i],     hz = g_gh[N + i];
    float in = g_gi[2 * N + i], hn = g_gh[2 * N + i];
    float r = 1.0f / (1.0f + expf(-(ir + hr)));
    float z = 1.0f / (1.0f + expf(-(iz + hz)));
    float nn = tanhf(in + r * hn);
    float hnew = (1.0f - z) * nn + z * h;
    g_sk[i] = hnew;

    float ad = fabsf(hnew - x);
    float pr = hnew * x;
    const float* w0 = W3 + (size_t)i * 3;
    const float* w1 = W3 + (size_t)(N + i) * 3;
    const float* w2 = W3 + (size_t)(2 * N + i) * 3;
    const float* w3 = W3 + (size_t)(3 * N + i) * 3;
    float l0 = w0[0] * hnew + w1[0] * x + w2[0] * ad + w3[0] * pr;
    float l1 = w0[1] * hnew + w1[1] * x + w2[1] * ad + w3[1] * pr;
    float l2 = w0[2] * hnew + w1[2] * x + w2[2] * ad + w3[2] * pr;
#pragma unroll
    for (int o = 16; o; o >>= 1) {
        l0 += __shfl_down_sync(0xffffffffu, l0, o);
        l1 += __shfl_down_sync(0xffffffffu, l1, o);
        l2 += __shfl_down_sync(0xffffffffu, l2, o);
    }
    if ((threadIdx.x & 31) == 0) {
        atomicAdd(&g_l3[step * 3 + 0], l0);
        atomicAdd(&g_l3[step * 3 + 1], l1);
        atomicAdd(&g_l3[step * 3 + 2], l2);
    }
}

// per-step label softmax + average
__global__ void final_kernel(float* __restrict__ out, const int* __restrict__ Kp) {
    if (threadIdx.x == 0) {
        int K = *Kp;
        float p0 = 0.f, p1 = 0.f, p2 = 0.f;
        for (int s = 0; s < K; s++) {
            float a = g_l3[s * 3 + 0], b = g_l3[s * 3 + 1], c = g_l3[s * 3 + 2];
            float m = fmaxf(a, fmaxf(b, c));
            float ea = expf(a - m), eb = expf(b - m), ec = expf(c - m);
            float sum = ea + eb + ec;
            p0 += ea / sum; p1 += eb / sum; p2 += ec / sum;
        }
        out[0] = p0 / (float)K;
        out[1] = p1 / (float)K;
        out[2] = p2 / (float)K;
    }
}

// ---------------- host launch ----------------
static cudaStream_t h_s2 = nullptr;
static cudaEvent_t h_evF = nullptr;   // fork (start -> s2)
static cudaEvent_t h_evA = nullptr;   // W2+Mp conversions done
static cudaEvent_t h_evB = nullptr;   // wih conversion done
static cudaEvent_t h_evS = nullptr;   // sk ready (main -> s2)
static cudaEvent_t h_evG = nullptr;   // gh ready (s2 -> main)
static bool h_tried = false;

extern "C" void kernel_launch(void* const* d_in, const int* in_sizes, int n_in,
                              void* d_out, int out_size) {
    const float* M_h   = (const float*)d_in[0];
    const float* M_p   = (const float*)d_in[1];
    const float* w1    = (const float*)d_in[2];
    const float* W2    = (const float*)d_in[3];
    const float* W3    = (const float*)d_in[4];
    const float* w_ih  = (const float*)d_in[5];
    const float* w_hh  = (const float*)d_in[6];
    const int*   Kp    = (const int*)d_in[7];
    float* out = (float*)d_out;

    float *t, *sk, *u, *xk;
    __half *wih_h, *whh_h, *w2_h, *mp_h;
    cudaGetSymbolAddress((void**)&t,     g_t);
    cudaGetSymbolAddress((void**)&sk,    g_sk);
    cudaGetSymbolAddress((void**)&u,     g_u);
    cudaGetSymbolAddress((void**)&xk,    g_xk);
    cudaGetSymbolAddress((void**)&wih_h, g_wih_h);
    cudaGetSymbolAddress((void**)&whh_h, g_whh_h);
    cudaGetSymbolAddress((void**)&w2_h,  g_w2_h);
    cudaGetSymbolAddress((void**)&mp_h,  g_mp_h);

    if (!h_tried) {
        h_tried = true;
        if (cudaStreamCreateWithFlags(&h_s2, cudaStreamNonBlocking) == cudaSuccess) {
            cudaEventCreateWithFlags(&h_evF, cudaEventDisableTiming);
            cudaEventCreateWithFlags(&h_evA, cudaEventDisableTiming);
            cudaEventCreateWithFlags(&h_evB, cudaEventDisableTiming);
            cudaEventCreateWithFlags(&h_evS, cudaEventDisableTiming);
            cudaEventCreateWithFlags(&h_evG, cudaEventDisableTiming);
        } else {
            h_s2 = nullptr;
        }
    }
    const bool dual = (h_s2 != nullptr);
    cudaStream_t s2 = dual ? h_s2 : (cudaStream_t)0;

    dim3 cgrid(N / 256, N / CCHUNK);    // fp32 colmv: (16, 128)
    dim3 cgridh(N / 512, N / CCHUNK);   // fp16 colmv: (8, 128)
    const int n8g = G * (N / 8);        // gate matrices
    const int n8n = N * (N / 8);        // square matrices

    // ---- fork: conversions on s2 (W2, Mp resident-first; then wih; whh last
    // ordered in-stream before the first whh_kernel) ----
    init_kernel<<<(N + 1023) / 1024, 1024>>>();
    if (dual) {
        cudaEventRecord(h_evF, 0);
        cudaStreamWaitEvent(s2, h_evF, 0);
    }
    convert_fp16_kernel<<<(n8n + 255) / 256, 256, 0, s2>>>(W2,  w2_h,  n8n, 1);
    convert_fp16_kernel<<<(n8n + 255) / 256, 256, 0, s2>>>(M_p, mp_h,  n8n, 1);
    if (dual) cudaEventRecord(h_evA, s2);
    convert_fp16_kernel<<<(n8g + 255) / 256, 256, 0, s2>>>(w_ih, wih_h, n8g, 0);
    if (dual) cudaEventRecord(h_evB, s2);
    convert_fp16_kernel<<<(n8g + 255) / 256, 256, 0, s2>>>(w_hh, whh_h, n8g, 0);

    // prologue: alpha logits -> stats -> sk0 = softmax(alpha) @ M_h (fp32)
    colmv_kernel<<<cgrid, 256>>>(M_h, w1, t, 0, Kp);
    stats_kernel<<<1, 1024>>>(t, sk, 0, Kp);
    colmv_exp_kernel<<<cgrid, 256>>>(M_h, t, sk, 0, Kp);
    if (dual) cudaEventRecord(h_evS, 0);   // sk ready

    const int MAX_STEPS = 8;
    for (int s = 0; s < MAX_STEPS; s++) {
        // side stream: gh = w_hh @ sk (whh conversion precedes in-stream)
        if (dual) cudaStreamWaitEvent(s2, h_evS, 0);
        whh_kernel<<<G / 8, 256, 0, s2>>>(s, Kp);
        if (dual) cudaEventRecord(h_evG, s2);

        // main: beta chain
        if (dual && s == 0) cudaStreamWaitEvent(0, h_evA, 0);        // need w2_h, mp_h
        k1u_kernel<<<N / 8, 256>>>(s, Kp);                           // u = W2_h@sk, zero t
        colmv_fp16_kernel<<<cgridh, 256>>>(mp_h, u, t, s, Kp);       // logits (fp16 M_p, L2)
        stats_kernel<<<1, 1024>>>(t, xk, s, Kp);                     // M, 1/S; zero xk
        colmv_exp_fp16_kernel<<<cgridh, 256>>>(mp_h, t, xk, s, Kp);  // xk = beta @ M_p
        if (dual && s == 0) cudaStreamWaitEvent(0, h_evB, 0);        // need wih_h now
        wih_kernel<<<G / 8, 256>>>(s, Kp);                           // gi = w_ih @ xk

        if (dual) cudaStreamWaitEvent(0, h_evG, 0);                  // join gh
        gru_kernel<<<16, 256>>>(W3, s, Kp);                          // sk update + l3[s]
        if (dual) cudaEventRecord(h_evS, 0);                         // sk ready
    }

    final_kernel<<<1, 32>>>(out, Kp);
}